// round 4
// baseline (speedup 1.0000x reference)
#include <cuda_runtime.h>
#include <cstddef>

// Sparsemax (alpha=2), fused single-DRAM-read gather with chunk-skip.
// While streaming the row, each warp tracks a running max and gathers values
// above (running max - 1) -- a superset of the true candidate set
// {x : x > rowmax-1} (every reference bisection iterate exceeds rowmax-1, so
// other elements contribute 0 to f(tau)). The per-chunk fast path is one
// ballot on the 8-element per-thread max; only chunks containing a qualifying
// element pay the full warp-max + per-element compaction.
// tau: closed-form sorted-threshold rule for K<=32 (typical K ~ 8-30),
// warp bisection for K<=512, full-row block bisection as overflow fallback.

#define SPM_D   32000
#define SPM_D4  (SPM_D / 4)      // 8000 float4
#define SPM_NT  256
#define SPM_NW  (SPM_NT / 32)    // 8 warps
#define WBUF    256              // per-warp superset buffer
#define FCAP    512              // filtered candidate cap

#define NEG_INF (-3.402823466e38f)
#define FULL    0xffffffffu

__device__ __forceinline__ float warp_max(float v) {
#pragma unroll
    for (int o = 16; o; o >>= 1) v = fmaxf(v, __shfl_xor_sync(FULL, v, o));
    return v;
}
__device__ __forceinline__ float warp_sum(float v) {
#pragma unroll
    for (int o = 16; o; o >>= 1) v += __shfl_xor_sync(FULL, v, o);
    return v;
}

__global__ __launch_bounds__(SPM_NT, 6)
void spm_kernel(const float* __restrict__ X, float* __restrict__ Y) {
    __shared__ float s_buf[SPM_NW][WBUF];
    __shared__ float s_filt[FCAP];
    __shared__ float s_wmax[SPM_NW];
    __shared__ int   s_cnt[SPM_NW];
    __shared__ float s_r[SPM_NW];
    __shared__ int   s_K, s_flag;
    __shared__ float s_tau, s_inv;

    const int tid  = threadIdx.x;
    const int lane = tid & 31;
    const int wid  = tid >> 5;
    const unsigned ltmask = (1u << lane) - 1u;
    const int row = blockIdx.x;

    const float4* __restrict__ x4 =
        reinterpret_cast<const float4*>(X + (size_t)row * (size_t)SPM_D);
    float4* __restrict__ y4 =
        reinterpret_cast<float4*>(Y + (size_t)row * (size_t)SPM_D);

    if (tid == 0) { s_K = 0; s_flag = 0; }

    // ---- Pass 1: stream row (DRAM) with chunk-skip superset gather ----
    float wmax = NEG_INF;
    float thr  = NEG_INF;
    int   cnt  = 0;

#define SPM_G(c)                                                               \
    {                                                                          \
        bool q = (c) > thr;                                                    \
        unsigned bb = __ballot_sync(FULL, q);                                  \
        if (q) {                                                               \
            int p = cnt + __popc(bb & ltmask);                                 \
            if (p < WBUF) s_buf[wid][p] = (c);                                 \
        }                                                                      \
        cnt += __popc(bb);                                                     \
    }

    // 16 iterations: i = tid + 512k covers [512k, 512k+256),
    // i+256 covers [512k+256, 512k+512); have1 boundary lands at tid==64
    // (a warp boundary) so all ballots stay warp-uniform.
#pragma unroll 1
    for (int k = 0; k < (SPM_D4 + 2 * SPM_NT - 1) / (2 * SPM_NT); ++k) {
        const int i = tid + k * 2 * SPM_NT;
        const bool have1 = (i + SPM_NT) < SPM_D4;   // warp-uniform

        float4 v0 = x4[i];
        float4 v1 = make_float4(NEG_INF, NEG_INF, NEG_INF, NEG_INF);
        if (have1) v1 = x4[i + SPM_NT];

        float m8 = fmaxf(fmaxf(v0.x, v0.y), fmaxf(v0.z, v0.w));
        m8 = fmaxf(m8, fmaxf(fmaxf(v1.x, v1.y), fmaxf(v1.z, v1.w)));

        // fast path: one ballot per 8 elements
        unsigned hit = __ballot_sync(FULL, m8 > thr);
        if (hit) {
            wmax = fmaxf(wmax, warp_max(m8));
            thr  = wmax - 1.0f;     // new thr <= rowmax-1, still a superset
            SPM_G(v0.x); SPM_G(v0.y); SPM_G(v0.z); SPM_G(v0.w);
            if (have1) {
                SPM_G(v1.x); SPM_G(v1.y); SPM_G(v1.z); SPM_G(v1.w);
            }
        }
    }
#undef SPM_G

    if (lane == 0) {
        s_wmax[wid] = wmax;
        s_cnt[wid]  = cnt;
        if (cnt > WBUF) s_flag = 1;
    }
    __syncthreads();

    float m = (lane < SPM_NW) ? s_wmax[lane] : NEG_INF;
    const float mxv   = warp_max(m);          // block max, redundant per warp
    const float thrF  = mxv - 1.0f;
    const float inv_d = 1.0f / (float)SPM_D;

    bool need_full = (s_flag != 0);
    float tau = 0.0f, inv = 1.0f;

    if (!need_full) {
        // ---- Filter superset -> true candidates (> rowmax - 1) ----
        const int c = s_cnt[wid];
        for (int i = lane; i < c; i += 32) {
            float val = s_buf[wid][i];
            if (val > thrF) {
                int p = atomicAdd(&s_K, 1);
                if (p < FCAP) s_filt[p] = val;
            }
        }
        __syncthreads();
        const int K = s_K;   // uniform

        if (K >= 1 && K <= 32) {
            // ---- Closed-form threshold, redundant per-warp (no barrier) ----
            float z = (lane < K) ? s_filt[lane] : NEG_INF;
            // bitonic sort, descending
#pragma unroll
            for (int kk = 2; kk <= 32; kk <<= 1) {
#pragma unroll
                for (int j = kk >> 1; j > 0; j >>= 1) {
                    float o = __shfl_xor_sync(FULL, z, j);
                    bool lower   = (lane & j) == 0;
                    bool descBlk = (lane & kk) == 0;
                    z = (lower == descBlk) ? fmaxf(z, o) : fminf(z, o);
                }
            }
            // inclusive prefix sum
            float S = z;
#pragma unroll
            for (int o = 1; o < 32; o <<= 1) {
                float t = __shfl_up_sync(FULL, S, o);
                if (lane >= o) S += t;
            }
            float kf = (float)(lane + 1);
            unsigned bal = __ballot_sync(FULL, fmaf(kf, z, 1.0f) > S);
            int h = 31 - __clz(bal);          // lane 0 always qualifies
            tau = __shfl_sync(FULL, (S - 1.0f) / kf, h);
            float s = warp_sum(fmaxf(z - tau, 0.0f));
            inv = 1.0f / s;
        } else if (K <= FCAP) {
            // ---- Reference bisection over candidates (warp 0) ----
            if (wid == 0) {
                float tlo = thrF;
                float dm  = (mxv - inv_d) - tlo;
                float a = 0.0f;
                for (int i = lane; i < K; i += 32)
                    a += fmaxf(s_filt[i] - tlo, 0.0f);
                const float flo = warp_sum(a) - 1.0f;
                float tm = tlo, fm = flo;
                for (int it = 0; it < 50; ++it) {
                    dm *= 0.5f;
                    tm = tlo + dm;
                    float s = 0.0f;
                    for (int i = lane; i < K; i += 32)
                        s += fmaxf(s_filt[i] - tm, 0.0f);
                    fm = warp_sum(s) - 1.0f;
                    if (fm * flo >= 0.0f) tlo = tm;
                }
                if (lane == 0) { s_tau = tm; s_inv = 1.0f / (fm + 1.0f); }
            }
            __syncthreads();
            tau = s_tau; inv = s_inv;
        } else {
            need_full = true;  // uniform
        }
    }

    if (need_full) {
        // ---- Correctness fallback: block bisection over full row (L2) ----
        float tlo = thrF;
        float dm  = (mxv - inv_d) - tlo;

        float a = 0.0f;
        for (int i = tid; i < SPM_D4; i += SPM_NT) {
            float4 v = x4[i];
            a += fmaxf(v.x - tlo, 0.0f) + fmaxf(v.y - tlo, 0.0f) +
                 fmaxf(v.z - tlo, 0.0f) + fmaxf(v.w - tlo, 0.0f);
        }
        a = warp_sum(a);
        if (lane == 0) s_r[wid] = a;
        __syncthreads();
        float r0 = (lane < SPM_NW) ? s_r[lane] : 0.0f;
        const float flo = warp_sum(r0) - 1.0f;

        float tm = tlo, fm = flo;
        for (int it = 0; it < 50; ++it) {
            dm *= 0.5f;
            tm = tlo + dm;
            float s = 0.0f;
            for (int i = tid; i < SPM_D4; i += SPM_NT) {
                float4 v = x4[i];
                s += fmaxf(v.x - tm, 0.0f) + fmaxf(v.y - tm, 0.0f) +
                     fmaxf(v.z - tm, 0.0f) + fmaxf(v.w - tm, 0.0f);
            }
            s = warp_sum(s);
            __syncthreads();
            if (lane == 0) s_r[wid] = s;
            __syncthreads();
            float rr = (lane < SPM_NW) ? s_r[lane] : 0.0f;
            fm = warp_sum(rr) - 1.0f;
            if (fm * flo >= 0.0f) tlo = tm;
        }
        tau = tm;
        inv = 1.0f / (fm + 1.0f);
    }

    // ---- Pass 2: L2 re-read + streaming write ----
#pragma unroll 4
    for (int i = tid; i < SPM_D4; i += SPM_NT) {
        float4 v = __ldcg(&x4[i]);
        float4 r;
        r.x = fmaxf(v.x - tau, 0.0f) * inv;
        r.y = fmaxf(v.y - tau, 0.0f) * inv;
        r.z = fmaxf(v.z - tau, 0.0f) * inv;
        r.w = fmaxf(v.w - tau, 0.0f) * inv;
        __stcs(&y4[i], r);
    }
}

extern "C" void kernel_launch(void* const* d_in, const int* in_sizes, int n_in,
                              void* d_out, int out_size) {
    const float* X = (const float*)d_in[0];
    float* Y       = (float*)d_out;
    const int rows = in_sizes[0] / SPM_D;

    spm_kernel<<<rows, SPM_NT>>>(X, Y);
}

// round 5
// speedup vs baseline: 1.0770x; 1.0770x over previous
#include <cuda_runtime.h>
#include <cstddef>

// Sparsemax (alpha=2), fused single-DRAM-read gather with chunk-skip,
// at 3 CTAs/SM so pass-2 re-reads stay L2-resident (57MB live << 126MB L2).
// While streaming the row, each warp tracks a running max and gathers values
// above (running max - 1) -- a superset of the true candidate set
// {x : x > rowmax-1} (every reference bisection iterate exceeds rowmax-1, so
// other elements contribute 0 to f(tau)). Fast path per 8 elements: one
// ballot on the per-thread max; only qualifying chunks pay the warp-max +
// per-element compaction.
// tau: closed-form sorted-threshold rule for K<=32 (typical K ~ 8-30),
// warp bisection for K<=512, full-row block bisection as overflow fallback.

#define SPM_D   32000
#define SPM_D4  (SPM_D / 4)      // 8000 float4
#define SPM_NT  512
#define SPM_NW  (SPM_NT / 32)    // 16 warps
#define WBUF    256              // per-warp superset buffer
#define FCAP    512              // filtered candidate cap

#define NEG_INF (-3.402823466e38f)
#define FULL    0xffffffffu

__device__ __forceinline__ float warp_max(float v) {
#pragma unroll
    for (int o = 16; o; o >>= 1) v = fmaxf(v, __shfl_xor_sync(FULL, v, o));
    return v;
}
__device__ __forceinline__ float warp_sum(float v) {
#pragma unroll
    for (int o = 16; o; o >>= 1) v += __shfl_xor_sync(FULL, v, o);
    return v;
}

__global__ __launch_bounds__(SPM_NT, 3)
void spm_kernel(const float* __restrict__ X, float* __restrict__ Y) {
    __shared__ float s_buf[SPM_NW][WBUF];
    __shared__ float s_filt[FCAP];
    __shared__ float s_wmax[SPM_NW];
    __shared__ int   s_cnt[SPM_NW];
    __shared__ float s_r[SPM_NW];
    __shared__ int   s_K, s_flag;
    __shared__ float s_tau, s_inv;

    const int tid  = threadIdx.x;
    const int lane = tid & 31;
    const int wid  = tid >> 5;
    const unsigned ltmask = (1u << lane) - 1u;
    const int row = blockIdx.x;

    const float4* __restrict__ x4 =
        reinterpret_cast<const float4*>(X + (size_t)row * (size_t)SPM_D);
    float4* __restrict__ y4 =
        reinterpret_cast<float4*>(Y + (size_t)row * (size_t)SPM_D);

    if (tid == 0) { s_K = 0; s_flag = 0; }

    // ---- Pass 1: stream row (DRAM) with chunk-skip superset gather ----
    float wmax = NEG_INF;
    float thr  = NEG_INF;
    int   cnt  = 0;

#define SPM_G(c)                                                               \
    {                                                                          \
        bool q = (c) > thr;                                                    \
        unsigned bb = __ballot_sync(FULL, q);                                  \
        if (q) {                                                               \
            int p = cnt + __popc(bb & ltmask);                                 \
            if (p < WBUF) s_buf[wid][p] = (c);                                 \
        }                                                                      \
        cnt += __popc(bb);                                                     \
    }

    // i = tid + 1024k and i + 512. Tail: last iter's have1 boundary lands at
    // tid==320 (a warp boundary), so all ballots stay warp-uniform.
#pragma unroll 1
    for (int k = 0; k < (SPM_D4 + 2 * SPM_NT - 1) / (2 * SPM_NT); ++k) {
        const int i = tid + k * 2 * SPM_NT;
        const bool have1 = (i + SPM_NT) < SPM_D4;   // warp-uniform

        float4 v0 = x4[i];
        float4 v1 = make_float4(NEG_INF, NEG_INF, NEG_INF, NEG_INF);
        if (have1) v1 = x4[i + SPM_NT];

        float m8 = fmaxf(fmaxf(v0.x, v0.y), fmaxf(v0.z, v0.w));
        m8 = fmaxf(m8, fmaxf(fmaxf(v1.x, v1.y), fmaxf(v1.z, v1.w)));

        // fast path: one ballot per 8 elements
        unsigned hit = __ballot_sync(FULL, m8 > thr);
        if (hit) {
            wmax = fmaxf(wmax, warp_max(m8));
            thr  = wmax - 1.0f;     // thr <= rowmax-1, still a superset
            SPM_G(v0.x); SPM_G(v0.y); SPM_G(v0.z); SPM_G(v0.w);
            if (have1) {
                SPM_G(v1.x); SPM_G(v1.y); SPM_G(v1.z); SPM_G(v1.w);
            }
        }
    }
#undef SPM_G

    if (lane == 0) {
        s_wmax[wid] = wmax;
        s_cnt[wid]  = cnt;
        if (cnt > WBUF) s_flag = 1;
    }
    __syncthreads();

    float m = (lane < SPM_NW) ? s_wmax[lane] : NEG_INF;
    const float mxv   = warp_max(m);          // block max, redundant per warp
    const float thrF  = mxv - 1.0f;
    const float inv_d = 1.0f / (float)SPM_D;

    bool need_full = (s_flag != 0);
    float tau = 0.0f, inv = 1.0f;

    if (!need_full) {
        // ---- Filter superset -> true candidates (> rowmax - 1) ----
        const int c = s_cnt[wid];
        for (int i = lane; i < c; i += 32) {
            float val = s_buf[wid][i];
            if (val > thrF) {
                int p = atomicAdd(&s_K, 1);
                if (p < FCAP) s_filt[p] = val;
            }
        }
        __syncthreads();
        const int K = s_K;   // uniform

        if (K >= 1 && K <= 32) {
            // ---- Closed-form threshold, redundant per-warp (no barrier) ----
            float z = (lane < K) ? s_filt[lane] : NEG_INF;
            // bitonic sort, descending
#pragma unroll
            for (int kk = 2; kk <= 32; kk <<= 1) {
#pragma unroll
                for (int j = kk >> 1; j > 0; j >>= 1) {
                    float o = __shfl_xor_sync(FULL, z, j);
                    bool lower   = (lane & j) == 0;
                    bool descBlk = (lane & kk) == 0;
                    z = (lower == descBlk) ? fmaxf(z, o) : fminf(z, o);
                }
            }
            // inclusive prefix sum
            float S = z;
#pragma unroll
            for (int o = 1; o < 32; o <<= 1) {
                float t = __shfl_up_sync(FULL, S, o);
                if (lane >= o) S += t;
            }
            float kf = (float)(lane + 1);
            unsigned bal = __ballot_sync(FULL, fmaf(kf, z, 1.0f) > S);
            int h = 31 - __clz(bal);          // lane 0 always qualifies
            tau = __shfl_sync(FULL, (S - 1.0f) / kf, h);
            float s = warp_sum(fmaxf(z - tau, 0.0f));
            inv = 1.0f / s;
        } else if (K <= FCAP) {
            // ---- Reference bisection over candidates (warp 0) ----
            if (wid == 0) {
                float tlo = thrF;
                float dm  = (mxv - inv_d) - tlo;
                float a = 0.0f;
                for (int i = lane; i < K; i += 32)
                    a += fmaxf(s_filt[i] - tlo, 0.0f);
                const float flo = warp_sum(a) - 1.0f;
                float tm = tlo, fm = flo;
                for (int it = 0; it < 50; ++it) {
                    dm *= 0.5f;
                    tm = tlo + dm;
                    float s = 0.0f;
                    for (int i = lane; i < K; i += 32)
                        s += fmaxf(s_filt[i] - tm, 0.0f);
                    fm = warp_sum(s) - 1.0f;
                    if (fm * flo >= 0.0f) tlo = tm;
                }
                if (lane == 0) { s_tau = tm; s_inv = 1.0f / (fm + 1.0f); }
            }
            __syncthreads();
            tau = s_tau; inv = s_inv;
        } else {
            need_full = true;  // uniform
        }
    }

    if (need_full) {
        // ---- Correctness fallback: block bisection over full row (L2) ----
        float tlo = thrF;
        float dm  = (mxv - inv_d) - tlo;

        float a = 0.0f;
        for (int i = tid; i < SPM_D4; i += SPM_NT) {
            float4 v = x4[i];
            a += fmaxf(v.x - tlo, 0.0f) + fmaxf(v.y - tlo, 0.0f) +
                 fmaxf(v.z - tlo, 0.0f) + fmaxf(v.w - tlo, 0.0f);
        }
        a = warp_sum(a);
        if (lane == 0) s_r[wid] = a;
        __syncthreads();
        float r0 = (lane < SPM_NW) ? s_r[lane] : 0.0f;
        const float flo = warp_sum(r0) - 1.0f;

        float tm = tlo, fm = flo;
        for (int it = 0; it < 50; ++it) {
            dm *= 0.5f;
            tm = tlo + dm;
            float s = 0.0f;
            for (int i = tid; i < SPM_D4; i += SPM_NT) {
                float4 v = x4[i];
                s += fmaxf(v.x - tm, 0.0f) + fmaxf(v.y - tm, 0.0f) +
                     fmaxf(v.z - tm, 0.0f) + fmaxf(v.w - tm, 0.0f);
            }
            s = warp_sum(s);
            __syncthreads();
            if (lane == 0) s_r[wid] = s;
            __syncthreads();
            float rr = (lane < SPM_NW) ? s_r[lane] : 0.0f;
            fm = warp_sum(rr) - 1.0f;
            if (fm * flo >= 0.0f) tlo = tm;
        }
        tau = tm;
        inv = 1.0f / (fm + 1.0f);
    }

    // ---- Pass 2: L2 re-read + streaming write ----
#pragma unroll 4
    for (int i = tid; i < SPM_D4; i += SPM_NT) {
        float4 v = __ldcg(&x4[i]);
        float4 r;
        r.x = fmaxf(v.x - tau, 0.0f) * inv;
        r.y = fmaxf(v.y - tau, 0.0f) * inv;
        r.z = fmaxf(v.z - tau, 0.0f) * inv;
        r.w = fmaxf(v.w - tau, 0.0f) * inv;
        __stcs(&y4[i], r);
    }
}

extern "C" void kernel_launch(void* const* d_in, const int* in_sizes, int n_in,
                              void* d_out, int out_size) {
    const float* X = (const float*)d_in[0];
    float* Y       = (float*)d_out;
    const int rows = in_sizes[0] / SPM_D;

    spm_kernel<<<rows, SPM_NT>>>(X, Y);
}

// round 6
// speedup vs baseline: 1.1946x; 1.1092x over previous
#include <cuda_runtime.h>
#include <cstddef>

// Sparsemax (alpha=2), 3-pass per row with 72KB/CTA smem row cache.
// Pass 1: pure streaming load + max (no ballots -- keeps MLP high), caching
//   the first 4608 float4 (72KB) of the row in shared memory (__ldcs so the
//   cached part never occupies L2; the 54KB remainder uses default loads and
//   stays L2-resident for re-reads).
// Pass 2: gather candidates {x > rowmax-1} (superset of everything that can
//   contribute to the reference bisection's f(tau)) from smem + L2 with
//   rare-hit conditional atomics.
// tau: closed-form sorted-threshold rule for K<=32 (typical K ~ 8-30),
//   computed redundantly in every warp (no broadcast barrier); reference
//   bisection over candidates for K<=512; full-row bisection fallback.
// Pass 3: smem + L2 re-read, streaming stores.

#define SPM_D   32000
#define SPM_D4  (SPM_D / 4)      // 8000 float4
#define SPM_C4  4608             // cached float4 (72KB), multiple of NT
#define SPM_NT  512
#define SPM_NW  (SPM_NT / 32)    // 16 warps
#define FCAP    512

#define NEG_INF (-3.402823466e38f)
#define FULL    0xffffffffu

__device__ __forceinline__ float warp_max(float v) {
#pragma unroll
    for (int o = 16; o; o >>= 1) v = fmaxf(v, __shfl_xor_sync(FULL, v, o));
    return v;
}
__device__ __forceinline__ float warp_sum(float v) {
#pragma unroll
    for (int o = 16; o; o >>= 1) v += __shfl_xor_sync(FULL, v, o);
    return v;
}

extern __shared__ float4 s_x4[];   // SPM_C4 float4 = 72KB

__global__ __launch_bounds__(SPM_NT, 3)
void spm_kernel(const float* __restrict__ X, float* __restrict__ Y) {
    __shared__ float s_filt[FCAP];
    __shared__ float s_wmax[SPM_NW];
    __shared__ float s_r[SPM_NW];
    __shared__ int   s_K;
    __shared__ float s_tau, s_inv;

    const int tid  = threadIdx.x;
    const int lane = tid & 31;
    const int wid  = tid >> 5;
    const int row  = blockIdx.x;

    const float4* __restrict__ x4 =
        reinterpret_cast<const float4*>(X + (size_t)row * (size_t)SPM_D);
    float4* __restrict__ y4 =
        reinterpret_cast<float4*>(Y + (size_t)row * (size_t)SPM_D);

    if (tid == 0) s_K = 0;

    // ---- Pass 1: stream row, max, cache first 72KB in smem ----
    float mx = NEG_INF;
#pragma unroll 4
    for (int i = tid; i < SPM_C4; i += SPM_NT) {
        float4 v = __ldcs(&x4[i]);              // cached in smem; skip L2 reuse
        s_x4[i] = v;
        mx = fmaxf(mx, fmaxf(fmaxf(v.x, v.y), fmaxf(v.z, v.w)));
    }
#pragma unroll 4
    for (int i = SPM_C4 + tid; i < SPM_D4; i += SPM_NT) {
        float4 v = x4[i];                       // default: keep in L2
        mx = fmaxf(mx, fmaxf(fmaxf(v.x, v.y), fmaxf(v.z, v.w)));
    }
    mx = warp_max(mx);
    if (lane == 0) s_wmax[wid] = mx;
    __syncthreads();                            // barrier 1 (also orders s_K)

    float m = (lane < SPM_NW) ? s_wmax[lane] : NEG_INF;
    const float mxv   = warp_max(m);            // block max, redundant per warp
    const float thrF  = mxv - 1.0f;
    const float inv_d = 1.0f / (float)SPM_D;

    // ---- Pass 2: gather candidates > rowmax-1 (rare-hit atomics) ----
#pragma unroll 2
    for (int i = tid; i < SPM_C4; i += SPM_NT) {
        float4 v = s_x4[i];
        if (v.x > thrF) { int p = atomicAdd(&s_K, 1); if (p < FCAP) s_filt[p] = v.x; }
        if (v.y > thrF) { int p = atomicAdd(&s_K, 1); if (p < FCAP) s_filt[p] = v.y; }
        if (v.z > thrF) { int p = atomicAdd(&s_K, 1); if (p < FCAP) s_filt[p] = v.z; }
        if (v.w > thrF) { int p = atomicAdd(&s_K, 1); if (p < FCAP) s_filt[p] = v.w; }
    }
#pragma unroll 2
    for (int i = SPM_C4 + tid; i < SPM_D4; i += SPM_NT) {
        float4 v = __ldcg(&x4[i]);
        if (v.x > thrF) { int p = atomicAdd(&s_K, 1); if (p < FCAP) s_filt[p] = v.x; }
        if (v.y > thrF) { int p = atomicAdd(&s_K, 1); if (p < FCAP) s_filt[p] = v.y; }
        if (v.z > thrF) { int p = atomicAdd(&s_K, 1); if (p < FCAP) s_filt[p] = v.z; }
        if (v.w > thrF) { int p = atomicAdd(&s_K, 1); if (p < FCAP) s_filt[p] = v.w; }
    }
    __syncthreads();                            // barrier 2
    const int K = s_K;                          // uniform; K >= 1 always

    float tau, inv;
    bool need_full = false;

    if (K <= 32) {
        // ---- Closed-form threshold, redundant per-warp (no barrier) ----
        float z = (lane < K) ? s_filt[lane] : NEG_INF;
        // bitonic sort, descending
#pragma unroll
        for (int kk = 2; kk <= 32; kk <<= 1) {
#pragma unroll
            for (int j = kk >> 1; j > 0; j >>= 1) {
                float o = __shfl_xor_sync(FULL, z, j);
                bool lower   = (lane & j) == 0;
                bool descBlk = (lane & kk) == 0;
                z = (lower == descBlk) ? fmaxf(z, o) : fminf(z, o);
            }
        }
        // inclusive prefix sum
        float S = z;
#pragma unroll
        for (int o = 1; o < 32; o <<= 1) {
            float t = __shfl_up_sync(FULL, S, o);
            if (lane >= o) S += t;
        }
        float kf = (float)(lane + 1);
        unsigned bal = __ballot_sync(FULL, fmaf(kf, z, 1.0f) > S);
        int h = 31 - __clz(bal);                // lane 0 always qualifies
        tau = __shfl_sync(FULL, (S - 1.0f) / kf, h);
        float s = warp_sum(fmaxf(z - tau, 0.0f));
        inv = 1.0f / s;
    } else if (K <= FCAP) {
        // ---- Reference bisection over candidates (warp 0) ----
        if (wid == 0) {
            float tlo = thrF;
            float dm  = (mxv - inv_d) - tlo;
            float a = 0.0f;
            for (int i = lane; i < K; i += 32)
                a += fmaxf(s_filt[i] - tlo, 0.0f);
            const float flo = warp_sum(a) - 1.0f;
            float tm = tlo, fm = flo;
            for (int it = 0; it < 50; ++it) {
                dm *= 0.5f;
                tm = tlo + dm;
                float s = 0.0f;
                for (int i = lane; i < K; i += 32)
                    s += fmaxf(s_filt[i] - tm, 0.0f);
                fm = warp_sum(s) - 1.0f;
                if (fm * flo >= 0.0f) tlo = tm;
            }
            if (lane == 0) { s_tau = tm; s_inv = 1.0f / (fm + 1.0f); }
        }
        __syncthreads();
        tau = s_tau; inv = s_inv;
    } else {
        need_full = true;                        // uniform
        tau = 0.0f; inv = 1.0f;
    }

    if (need_full) {
        // ---- Correctness fallback: block bisection, smem + L2 row ----
        float tlo = thrF;
        float dm  = (mxv - inv_d) - tlo;

        float a = 0.0f;
        for (int i = tid; i < SPM_D4; i += SPM_NT) {
            float4 v = (i < SPM_C4) ? s_x4[i] : __ldcg(&x4[i]);
            a += fmaxf(v.x - tlo, 0.0f) + fmaxf(v.y - tlo, 0.0f) +
                 fmaxf(v.z - tlo, 0.0f) + fmaxf(v.w - tlo, 0.0f);
        }
        a = warp_sum(a);
        if (lane == 0) s_r[wid] = a;
        __syncthreads();
        float r0 = (lane < SPM_NW) ? s_r[lane] : 0.0f;
        const float flo = warp_sum(r0) - 1.0f;

        float tm = tlo, fm = flo;
        for (int it = 0; it < 50; ++it) {
            dm *= 0.5f;
            tm = tlo + dm;
            float s = 0.0f;
            for (int i = tid; i < SPM_D4; i += SPM_NT) {
                float4 v = (i < SPM_C4) ? s_x4[i] : __ldcg(&x4[i]);
                s += fmaxf(v.x - tm, 0.0f) + fmaxf(v.y - tm, 0.0f) +
                     fmaxf(v.z - tm, 0.0f) + fmaxf(v.w - tm, 0.0f);
            }
            s = warp_sum(s);
            __syncthreads();
            if (lane == 0) s_r[wid] = s;
            __syncthreads();
            float rr = (lane < SPM_NW) ? s_r[lane] : 0.0f;
            fm = warp_sum(rr) - 1.0f;
            if (fm * flo >= 0.0f) tlo = tm;
        }
        tau = tm;
        inv = 1.0f / (fm + 1.0f);
    }

    // ---- Pass 3: smem + L2 re-read, streaming writes ----
#pragma unroll 4
    for (int i = tid; i < SPM_C4; i += SPM_NT) {
        float4 v = s_x4[i];
        float4 r;
        r.x = fmaxf(v.x - tau, 0.0f) * inv;
        r.y = fmaxf(v.y - tau, 0.0f) * inv;
        r.z = fmaxf(v.z - tau, 0.0f) * inv;
        r.w = fmaxf(v.w - tau, 0.0f) * inv;
        __stcs(&y4[i], r);
    }
#pragma unroll 4
    for (int i = SPM_C4 + tid; i < SPM_D4; i += SPM_NT) {
        float4 v = __ldcg(&x4[i]);
        float4 r;
        r.x = fmaxf(v.x - tau, 0.0f) * inv;
        r.y = fmaxf(v.y - tau, 0.0f) * inv;
        r.z = fmaxf(v.z - tau, 0.0f) * inv;
        r.w = fmaxf(v.w - tau, 0.0f) * inv;
        __stcs(&y4[i], r);
    }
}

extern "C" void kernel_launch(void* const* d_in, const int* in_sizes, int n_in,
                              void* d_out, int out_size) {
    const float* X = (const float*)d_in[0];
    float* Y       = (float*)d_out;
    const int rows = in_sizes[0] / SPM_D;
    const int shmem = SPM_C4 * sizeof(float4);  // 72KB

    cudaFuncSetAttribute(spm_kernel,
                         cudaFuncAttributeMaxDynamicSharedMemorySize, shmem);
    spm_kernel<<<rows, SPM_NT, shmem>>>(X, Y);
}